// round 17
// baseline (speedup 1.0000x reference)
#include <cuda_runtime.h>
#include <cuda_bf16.h>
#include <math.h>
#include <stdint.h>

#define Bb 8
#define Hh 12
#define Nn 2048
#define Dm 768
#define HD 64
#define Mf 256
#define BH (Bb*Hh)

#define DN    0.35355339059327373f  /* 64^-0.25 */
#define RATIO 0.0625f               /* 256^-0.5 */
#define EPSV  1e-4f

typedef unsigned long long u64;

// ---------------- packed f32x2 helpers (FFMA2 path, sm_103a) -----------------
__device__ __forceinline__ u64 pk2(float lo, float hi) {
    u64 r; asm("mov.b64 %0, {%1, %2};" : "=l"(r) : "f"(lo), "f"(hi)); return r;
}
__device__ __forceinline__ u64 dupf(float v) {
    u64 r; asm("mov.b64 %0, {%1, %1};" : "=l"(r) : "f"(v)); return r;
}
__device__ __forceinline__ void fma2(u64& d, u64 a, u64 b) {
    asm("fma.rn.f32x2 %0, %1, %2, %0;" : "+l"(d) : "l"(a), "l"(b));
}
__device__ __forceinline__ float2 up2(u64 v) {
    float2 f; asm("mov.b64 {%0, %1}, %2;" : "=f"(f.x), "=f"(f.y) : "l"(v)); return f;
}

// ---------------- scratch (static device globals; no allocs allowed) ---------
__device__ float g_q[BH*Nn*HD];
__device__ float g_k[BH*Nn*HD];
__device__ float g_v[BH*Nn*HD];
__device__ float g_qp[BH*Nn*Mf];
__device__ float g_kp[BH*Nn*Mf];
__device__ float g_kmax[BH];
__device__ float g_ksum[BH*Mf];
__device__ float g_ctx[BH*Mf*HD];
// bf16 hi/lo splits for tensor-core GEMMs (x first, then reused for attn out)
__device__ __align__(16) __nv_bfloat16 g_xhi[Bb*Nn*Dm];
__device__ __align__(16) __nv_bfloat16 g_xlo[Bb*Nn*Dm];
__device__ __align__(16) __nv_bfloat16 g_wh[4*Dm*Dm];   // slots: Wq, Wk, Wv, Wo
__device__ __align__(16) __nv_bfloat16 g_wl[4*Dm*Dm];
__device__ __align__(16) __nv_bfloat16 g_ph[Mf*HD];     // proj hi/lo [m][d]
__device__ __align__(16) __nv_bfloat16 g_pl[Mf*HD];

__device__ __forceinline__ void atomicMaxFloat(float* addr, float val) {
    if (val >= 0.f) atomicMax((int*)addr, __float_as_int(val));
    else            atomicMin((unsigned int*)addr, __float_as_uint(val));
}

// ---------------- baseline-PTX tensor helpers (compute_103-safe) -------------
__device__ __forceinline__ uint32_t s2u(const void* p) {
    uint32_t a;
    asm("{ .reg .u64 t; cvta.to.shared.u64 t, %1; cvt.u32.u64 %0, t; }" : "=r"(a) : "l"(p));
    return a;
}
__device__ __forceinline__ void cpa16(uint32_t s, const void* g) {
    asm volatile("cp.async.cg.shared.global [%0], [%1], 16;" :: "r"(s), "l"(g));
}
__device__ __forceinline__ void cpcommit() {
    asm volatile("cp.async.commit_group;" ::: "memory");
}
template<int N> __device__ __forceinline__ void cpwait() {
    asm volatile("cp.async.wait_group %0;" :: "n"(N) : "memory");
}
__device__ __forceinline__ void ldm4(uint32_t a, uint32_t r[4]) {
    asm volatile("ldmatrix.sync.aligned.m8n8.x4.shared.b16 {%0,%1,%2,%3}, [%4];"
                 : "=r"(r[0]), "=r"(r[1]), "=r"(r[2]), "=r"(r[3]) : "r"(a));
}
__device__ __forceinline__ void mma16816(float* c, const uint32_t* a, const uint32_t* b) {
    asm volatile(
        "mma.sync.aligned.m16n8k16.row.col.f32.bf16.bf16.f32 "
        "{%0,%1,%2,%3}, {%4,%5,%6,%7}, {%8,%9}, {%0,%1,%2,%3};"
        : "+f"(c[0]), "+f"(c[1]), "+f"(c[2]), "+f"(c[3])
        : "r"(a[0]), "r"(a[1]), "r"(a[2]), "r"(a[3]), "r"(b[0]), "r"(b[1]));
}

// ---------------- init: zero accumulators, -inf maxes, split proj ------------
__global__ void init_kernel(const float* __restrict__ proj) {
    int i = blockIdx.x * blockDim.x + threadIdx.x;
    int stride = gridDim.x * blockDim.x;
    for (int j = i; j < BH*Mf*HD; j += stride) g_ctx[j] = 0.f;
    if (i < BH*Mf) g_ksum[i] = 0.f;
    if (i < BH)    g_kmax[i] = -INFINITY;
    if (i < Mf*HD) {
        float a = proj[i];
        __nv_bfloat16 h = __float2bfloat16(a);
        g_ph[i] = h;
        g_pl[i] = __float2bfloat16(a - __bfloat162float(h));
    }
}

// ---------------- bf16 hi/lo split kernels ------------------------------------
__device__ __forceinline__ void split1(float a, __nv_bfloat16& h, __nv_bfloat16& l) {
    h = __float2bfloat16(a);
    l = __float2bfloat16(a - __bfloat162float(h));
}
__global__ void split_x_kernel(const float* __restrict__ src) {
    int i = blockIdx.x * blockDim.x + threadIdx.x;
    float a = src[i];
    split1(a, g_xhi[i], g_xlo[i]);
}
__global__ void split_w_kernel(const float* __restrict__ src, int slot) {
    int i = blockIdx.x * blockDim.x + threadIdx.x;
    float a = src[i];
    size_t o = (size_t)slot * Dm * Dm + i;
    split1(a, g_wh[o], g_wl[o]);
}

// ---------------- mma.sync bf16x3 GEMM: C = A @ W^T + bias -------------------
// Tile 128x128, 8 warps (2x4), warp tile 64x32, Kc=32, 3-stage cp.async ring.
#define STG   32768
#define R_ALO 8192
#define R_BHI 16384
#define R_BLO 24576
#define NST   3
#define GSMEM (NST*STG)
#define NKC   24

template<int QKV>
__global__ __launch_bounds__(256) void gemm_mma(const float* __restrict__ b0_,
                                                const float* __restrict__ b1_,
                                                const float* __restrict__ b2_,
                                                float* __restrict__ Cout) {
    extern __shared__ char smem[];
    const uint32_t sb = s2u(smem);
    const int tid = threadIdx.x;

    int sel, nblk;
    if (QKV) { sel = blockIdx.x / 6; nblk = blockIdx.x % 6; }
    else     { sel = 3;              nblk = blockIdx.x; }
    const int m0 = blockIdx.y * 128, n0 = nblk * 128;
    const __nv_bfloat16* Wh = g_wh + (size_t)sel * Dm * Dm;
    const __nv_bfloat16* Wl = g_wl + (size_t)sel * Dm * Dm;

    const int lane = tid & 31, warp = tid >> 5;
    const int wm = warp >> 2, wn = warp & 3;
    const int li = lane & 7, mid = lane >> 3;
    const int frow = tid >> 2, fc = tid & 3;

    float acc[4][4][4];
#pragma unroll
    for (int i = 0; i < 4; i++)
#pragma unroll
        for (int j = 0; j < 4; j++)
#pragma unroll
            for (int k = 0; k < 4; k++) acc[i][j][k] = 0.f;

    int rA[4], sA[4];
#pragma unroll
    for (int mf = 0; mf < 4; mf++) {
        rA[mf] = wm*64 + mf*16 + li + ((mid & 1) << 3);
        sA[mf] = (rA[mf] >> 1) & 3;
    }
    const int cAadd = mid >> 1;
    int rB[2], sB[2];
#pragma unroll
    for (int nt = 0; nt < 2; nt++) {
        rB[nt] = wn*32 + nt*16 + li + ((mid >> 1) << 3);
        sB[nt] = (rB[nt] >> 1) & 3;
    }
    const int cBadd = mid & 1;

    auto fill = [&](int s, int kc) {
        const int k0 = kc * 32;
        const uint32_t st = sb + s * STG;
#pragma unroll
        for (int i = 0; i < 2; i++) {
            int row = frow + i*64;
            uint32_t off = row*64 + ((fc ^ ((row >> 1) & 3)) << 4);
            size_t aoff = (size_t)(m0 + row) * Dm + k0 + fc*8;
            size_t boff = (size_t)(n0 + row) * Dm + k0 + fc*8;
            cpa16(st + off,         g_xhi + aoff);
            cpa16(st + R_ALO + off, g_xlo + aoff);
            cpa16(st + R_BHI + off, Wh + boff);
            cpa16(st + R_BLO + off, Wl + boff);
        }
        cpcommit();
    };

    fill(0, 0);
    fill(1, 1);
    int stage = 0;
    for (int kc = 0; kc < NKC; kc++) {
        cpwait<1>();          // oldest pending group (this stage) is complete
        __syncthreads();      // all warps past compute of stage (kc-1)%3
        if (kc + 2 < NKC) fill((stage + 2) % NST, kc + 2);

        const uint32_t st = sb + stage * STG;
#pragma unroll
        for (int ks = 0; ks < 2; ks++) {
            const int cb = 2*ks;
            uint32_t offA[4];
#pragma unroll
            for (int mf = 0; mf < 4; mf++)
                offA[mf] = rA[mf]*64 + (((cb + cAadd) ^ sA[mf]) << 4);
            uint32_t offB[2];
#pragma unroll
            for (int nt = 0; nt < 2; nt++)
                offB[nt] = rB[nt]*64 + (((cb + cBadd) ^ sB[nt]) << 4);

            uint32_t bh[4][2], bl[4][2];
#pragma unroll
            for (int nt = 0; nt < 2; nt++) {
                uint32_t r[4];
                ldm4(st + R_BHI + offB[nt], r);
                bh[2*nt][0] = r[0]; bh[2*nt][1] = r[1];
                bh[2*nt+1][0] = r[2]; bh[2*nt+1][1] = r[3];
                ldm4(st + R_BLO + offB[nt], r);
                bl[2*nt][0] = r[0]; bl[2*nt][1] = r[1];
                bl[2*nt+1][0] = r[2]; bl[2*nt+1][1] = r[3];
            }
            uint32_t af[4][4];
#pragma unroll
            for (int mf = 0; mf < 4; mf++) ldm4(st + offA[mf], af[mf]);
#pragma unroll
            for (int mf = 0; mf < 4; mf++)
#pragma unroll
                for (int nf = 0; nf < 4; nf++) {
                    mma16816(acc[mf][nf], af[mf], bh[nf]);
                    mma16816(acc[mf][nf], af[mf], bl[nf]);
                }
#pragma unroll
            for (int mf = 0; mf < 4; mf++) ldm4(st + R_ALO + offA[mf], af[mf]);
#pragma unroll
            for (int mf = 0; mf < 4; mf++)
#pragma unroll
                for (int nf = 0; nf < 4; nf++)
                    mma16816(acc[mf][nf], af[mf], bh[nf]);
        }
        stage = (stage + 1) % NST;
    }

    const float* bias = QKV ? ((sel == 0) ? b0_ : (sel == 1) ? b1_ : b2_) : b0_;
    float* dst = QKV ? ((sel == 0) ? g_q : (sel == 1) ? g_k : g_v) : Cout;
#pragma unroll
    for (int mf = 0; mf < 4; mf++)
#pragma unroll
        for (int nf = 0; nf < 4; nf++) {
            int cnG = n0 + wn*32 + nf*8 + 2*(lane & 3);
            float2 bb = *(const float2*)(bias + cnG);
#pragma unroll
            for (int h2 = 0; h2 < 2; h2++) {
                int m = m0 + wm*64 + mf*16 + (lane >> 2) + 8*h2;
                float2 v;
                v.x = acc[mf][nf][2*h2]   + bb.x;
                v.y = acc[mf][nf][2*h2+1] + bb.y;
                if (QKV) {
                    int b = m >> 11, n = m & 2047, hh = cnG >> 6, dd = cnG & 63;
                    *(float2*)(dst + ((size_t)((b*Hh + hh)*Nn + n) << 6) + dd) = v;
                } else {
                    *(float2*)(dst + (size_t)m * Dm + cnG) = v;
                }
            }
        }
}

// ---------------- FAVOR+ feature maps via mma.sync bf16x3 --------------------
#define F_AHI 0
#define F_ALO 8192
#define F_BHI 16384
#define F_BLO 49152
#define F_DIAG 81920
#define F_RMAX 82432
#define FSMEM  (F_RMAX + 64*4*4)

template<int ISQ>
__global__ __launch_bounds__(256) void feat_mma() {
    extern __shared__ char smem[];
    const uint32_t sb = s2u(smem);
    float* s_diag = (float*)(smem + F_DIAG);
    float* s_rmax = (float*)(smem + F_RMAX);
    const int tid = threadIdx.x;
    const int bh = blockIdx.x;
    const int nbase = blockIdx.y * 64;
    const int lane = tid & 31, warp = tid >> 5;
    const int wm = warp >> 2, wn = warp & 3;
    const int li = lane & 7, mid = lane >> 3;

    {
        const float* src = (ISQ ? g_q : g_k) + (size_t)((bh*Nn + nbase) << 6);
        const int row = tid >> 2;
        const int cp = tid & 3;
        float dsum = 0.f;
#pragma unroll
        for (int i = 0; i < 2; i++) {
            int c = cp*2 + i;
            const float4* qr = (const float4*)(src + row*64 + c*8);
            float4 f0 = qr[0], f1 = qr[1];
            float t[8] = { f0.x*DN, f0.y*DN, f0.z*DN, f0.w*DN,
                           f1.x*DN, f1.y*DN, f1.z*DN, f1.w*DN };
            struct { __nv_bfloat16 v[8]; } hi8, lo8;
#pragma unroll
            for (int j = 0; j < 8; j++) {
                dsum += t[j]*t[j];
                hi8.v[j] = __float2bfloat16(t[j]);
                lo8.v[j] = __float2bfloat16(t[j] - __bfloat162float(hi8.v[j]));
            }
            uint32_t off = row*128 + ((c ^ (row & 7)) << 4);
            *(uint4*)(smem + F_AHI + off) = *(uint4*)&hi8;
            *(uint4*)(smem + F_ALO + off) = *(uint4*)&lo8;
        }
        dsum += __shfl_xor_sync(0xffffffffu, dsum, 1);
        dsum += __shfl_xor_sync(0xffffffffu, dsum, 2);
        if ((tid & 3) == 0) s_diag[row] = 0.5f * dsum;
    }
#pragma unroll
    for (int i = 0; i < 8; i++) {
        int idx = tid + 256*i;
        int rp = idx >> 3, c = idx & 7;
        uint32_t off = rp*128 + ((c ^ (rp & 7)) << 4);
        *(uint4*)(smem + F_BHI + off) = *(const uint4*)(g_ph + rp*64 + c*8);
        *(uint4*)(smem + F_BLO + off) = *(const uint4*)(g_pl + rp*64 + c*8);
    }
    __syncthreads();

    float acc[2][8][4];
#pragma unroll
    for (int i = 0; i < 2; i++)
#pragma unroll
        for (int j = 0; j < 8; j++)
#pragma unroll
            for (int k = 0; k < 4; k++) acc[i][j][k] = 0.f;

    int rA[2];
#pragma unroll
    for (int mf = 0; mf < 2; mf++) rA[mf] = wm*32 + mf*16 + li + ((mid & 1) << 3);
    const int cAadd = mid >> 1;
    int rB[4];
#pragma unroll
    for (int nt = 0; nt < 4; nt++) rB[nt] = wn*64 + nt*16 + li + ((mid >> 1) << 3);
    const int cBadd = mid & 1;

#pragma unroll
    for (int ks = 0; ks < 4; ks++) {
        const int cb = 2*ks;
        uint32_t bhf[8][2], blf[8][2];
#pragma unroll
        for (int nt = 0; nt < 4; nt++) {
            uint32_t off = rB[nt]*128 + (((cb + cBadd) ^ (rB[nt] & 7)) << 4);
            uint32_t r[4];
            ldm4(sb + F_BHI + off, r);
            bhf[2*nt][0] = r[0]; bhf[2*nt][1] = r[1];
            bhf[2*nt+1][0] = r[2]; bhf[2*nt+1][1] = r[3];
            ldm4(sb + F_BLO + off, r);
            blf[2*nt][0] = r[0]; blf[2*nt][1] = r[1];
            blf[2*nt+1][0] = r[2]; blf[2*nt+1][1] = r[3];
        }
        uint32_t af[2][4];
        uint32_t offA[2];
#pragma unroll
        for (int mf = 0; mf < 2; mf++) {
            offA[mf] = rA[mf]*128 + (((cb + cAadd) ^ (rA[mf] & 7)) << 4);
            ldm4(sb + F_AHI + offA[mf], af[mf]);
        }
#pragma unroll
        for (int mf = 0; mf < 2; mf++)
#pragma unroll
            for (int nf = 0; nf < 8; nf++) {
                mma16816(acc[mf][nf], af[mf], bhf[nf]);
                mma16816(acc[mf][nf], af[mf], blf[nf]);
            }
#pragma unroll
        for (int mf = 0; mf < 2; mf++) ldm4(sb + F_ALO + offA[mf], af[mf]);
#pragma unroll
        for (int mf = 0; mf < 2; mf++)
#pragma unroll
            for (int nf = 0; nf < 8; nf++)
                mma16816(acc[mf][nf], af[mf], bhf[nf]);
    }

    if (ISQ) {
#pragma unroll
        for (int mf = 0; mf < 2; mf++)
#pragma unroll
            for (int h = 0; h < 2; h++) {
                float m = -INFINITY;
#pragma unroll
                for (int nf = 0; nf < 8; nf++)
                    m = fmaxf(m, fmaxf(acc[mf][nf][2*h], acc[mf][nf][2*h+1]));
                m = fmaxf(m, __shfl_xor_sync(0xffffffffu, m, 1));
                m = fmaxf(m, __shfl_xor_sync(0xffffffffu, m, 2));
                if ((lane & 3) == 0) {
                    int r = wm*32 + mf*16 + (lane >> 2) + 8*h;
                    s_rmax[r*4 + wn] = m;
                }
            }
        __syncthreads();
#pragma unroll
        for (int mf = 0; mf < 2; mf++)
#pragma unroll
            for (int h = 0; h < 2; h++) {
                int r = wm*32 + mf*16 + (lane >> 2) + 8*h;
                float mx = fmaxf(fmaxf(s_rmax[r*4+0], s_rmax[r*4+1]),
                                 fmaxf(s_rmax[r*4+2], s_rmax[r*4+3]));
                float base = s_diag[r] + mx;
                float* op = g_qp + (size_t)(bh*Nn + nbase + r)*Mf + wn*64 + 2*(lane & 3);
#pragma unroll
                for (int nf = 0; nf < 8; nf++) {
                    float2 v;
                    v.x = RATIO*(__expf(acc[mf][nf][2*h]   - base) + EPSV);
                    v.y = RATIO*(__expf(acc[mf][nf][2*h+1] - base) + EPSV);
                    *(float2*)(op + nf*8) = v;
                }
            }
    } else {
        float wmax = -INFINITY;
#pragma unroll
        for (int mf = 0; mf < 2; mf++)
#pragma unroll
            for (int h = 0; h < 2; h++) {
                int r = wm*32 + mf*16 + (lane >> 2) + 8*h;
                float dg = s_diag[r];
                float* op = g_kp + (size_t)(bh*Nn + nbase + r)*Mf + wn*64 + 2*(lane & 3);
#pragma unroll
                for (int nf = 0; nf < 8; nf++) {
                    float a0 = acc[mf][nf][2*h], a1 = acc[mf][nf][2*h+1];
                    wmax = fmaxf(wmax, fmaxf(a0, a1));
                    float2 v; v.x = a0 - dg; v.y = a1 - dg;
                    *(float2*)(op + nf*8) = v;
                }
            }
#pragma unroll
        for (int o = 16; o > 0; o >>= 1)
            wmax = fmaxf(wmax, __shfl_xor_sync(0xffffffffu, wmax, o));
        __shared__ float s_wm[8];
        if (lane == 0) s_wm[warp] = wmax;
        __syncthreads();
        if (tid == 0) {
            float m = s_wm[0];
#pragma unroll
            for (int w = 1; w < 8; w++) m = fmaxf(m, s_wm[w]);
            atomicMaxFloat(&g_kmax[bh], m);
        }
    }
}

// ---------------- ctx = exp(kp)^T @ v per (b,h), fused exp + ksum ------------
__global__ __launch_bounds__(256) void ctx_kernel() {
    const int bh = blockIdx.x;
    const int nbase = blockIdx.y * 256;
    __shared__ float ks_[16][256];
    __shared__ float vs[16][64];
    const int tid = threadIdx.x;
    const int tm = tid & 31, td = tid >> 5;
    const float kmax = g_kmax[bh];

    float ksum_p[4] = {0.f, 0.f, 0.f, 0.f};

    u64 acc2[8][4];
#pragma unroll
    for (int i = 0; i < 8; i++)
#pragma unroll
        for (int j = 0; j < 4; j++) acc2[i][j] = 0ULL;

    for (int t = 0; t < 16; t++) {
        int nb = nbase + t * 16;
        __syncthreads();
#pragma unroll
        for (int q = 0; q < 4; q++) {
            int t4 = tid + q*256;
            int r = t4 >> 6, c4 = (t4 & 63) * 4;
            float4 v = *(const float4*)(g_kp + (size_t)(bh*Nn + nb + r)*Mf + c4);
            v.x = RATIO*(__expf(v.x - kmax) + EPSV);
            v.y = RATIO*(__expf(v.y - kmax) + EPSV);
            v.z = RATIO*(__expf(v.z - kmax) + EPSV);
            v.w = RATIO*(__expf(v.w - kmax) + EPSV);
            ksum_p[0] += v.x; ksum_p[1] += v.y; ksum_p[2] += v.z; ksum_p[3] += v.w;
            *(float4*)&ks_[r][c4] = v;
        }
        {
            int r = tid >> 4, c4 = (tid & 15) * 4;
            *(float4*)&vs[r][c4] = *(const float4*)(g_v + (size_t)((bh*Nn + nb + r) << 6) + c4);
        }
        __syncthreads();
#pragma unroll
        for (int i = 0; i < 16; i++) {
            const u64* v0 = (const u64*)&vs[i][td*8];
            u64 bp0 = v0[0], bp1 = v0[1], bp2 = v0[2], bp3 = v0[3];
#pragma unroll
            for (int mi = 0; mi < 8; mi++) {
                u64 a = dupf(ks_[i][tm + 32*mi]);
                fma2(acc2[mi][0], a, bp0);
                fma2(acc2[mi][1], a, bp1);
                fma2(acc2[mi][2], a, bp2);
                fma2(acc2[mi][3], a, bp3);
            }
        }
    }
#pragma unroll
    for (int j = 0; j < 4; j++)
        atomicAdd(&g_ksum[bh*Mf + (tid & 63)*4 + j], ksum_p[j]);
#pragma unroll
    for (int mi = 0; mi < 8; mi++) {
        int m = tm + 32*mi;
#pragma unroll
        for (int dp_ = 0; dp_ < 4; dp_++) {
            float2 c = up2(acc2[mi][dp_]);
            atomicAdd(&g_ctx[(size_t)(bh*Mf + m)*HD + td*8 + dp_*2 + 0], c.x);
            atomicAdd(&g_ctx[(size_t)(bh*Mf + m)*HD + td*8 + dp_*2 + 1], c.y);
        }
    }
}

// ---------------- out = (qp @ ctx) * 1/(qp @ ksum) -> bf16 hi/lo splits ------
__global__ __launch_bounds__(256) void attn_out_kernel() {
    const int bh = blockIdx.x;
    const int n0 = blockIdx.y * 128;
    __shared__ float qs[8][128];
    __shared__ float cs[8][64];
    __shared__ float ksm[8];
    const int tid = threadIdx.x;
    const int ty = tid >> 4, tx = tid & 15;

    u64 acc2[8][2]; float dp[8];
#pragma unroll
    for (int i = 0; i < 8; i++) {
        dp[i] = 0.f;
        acc2[i][0] = 0ULL; acc2[i][1] = 0ULL;
    }

    for (int mt = 0; mt < 32; mt++) {
        int m0 = mt * 8;
        __syncthreads();
        {
            int row = tid >> 1, k4 = (tid & 1) * 4;
            float4 v = *(const float4*)(g_qp + (size_t)(bh*Nn + n0 + row)*Mf + m0 + k4);
            qs[k4+0][row] = v.x; qs[k4+1][row] = v.y;
            qs[k4+2][row] = v.z; qs[k4+3][row] = v.w;
        }
        if (tid < 128) {
            int kr = tid >> 4, c4 = (tid & 15) * 4;
            *(float4*)&cs[kr][c4] = *(const float4*)(g_ctx + (size_t)(bh*Mf + m0 + kr)*HD + c4);
        }
        if (tid < 8) ksm[tid] = g_ksum[bh*Mf + m0 + tid];
        __syncthreads();
#pragma unroll
        for (int kk = 0; kk < 8; kk++) {
            float af[8];
            *(float4*)&af[0] = *(const float4*)&qs[kk][ty*4];
            *(float4*)&af[4] = *(const float4*)&qs[kk][64 + ty*4];
            const u64* bq_ = (const u64*)&cs[kk][tx*4];
            u64 bp0 = bq_[0], bp1 = bq_[1];
            float kv = ksm[kk];
#pragma unroll
            for (int i = 0; i < 8; i++) {
                dp[i] = fmaf(af[i], kv, dp[i]);
                u64 a = dupf(af[i]);
                fma2(acc2[i][0], a, bp0);
                fma2(acc2[i][1], a, bp1);
            }
        }
    }

    const int b_ = bh / Hh, h = bh % Hh;
#pragma unroll
    for (int i = 0; i < 8; i++) {
        int row = (i < 4) ? (ty*4 + i) : (64 + ty*4 + (i - 4));
        int n = n0 + row;
        float dinv = 1.0f / dp[i];
        float2 c0 = up2(acc2[i][0]);
        float2 c1 = up2(acc2[i][1]);
        float v[4] = { c0.x*dinv, c0.y*dinv, c1.x*dinv, c1.y*dinv };
        struct { __nv_bfloat16 b[4]; } hi4, lo4;
#pragma unroll
        for (int j = 0; j < 4; j++) {
            hi4.b[j] = __float2bfloat16(v[j]);
            lo4.b[j] = __float2bfloat16(v[j] - __bfloat162float(hi4.b[j]));
        }
        size_t o = (size_t)(b_*Nn + n)*Dm + h*64 + tx*4;
        *(uint2*)(g_xhi + o) = *(uint2*)&hi4;
        *(uint2*)(g_xlo + o) = *(uint2*)&lo4;
    }
}

// ---------------- launch ------------------------------------------------------
extern "C" void kernel_launch(void* const* d_in, const int* in_sizes, int n_in,
                              void* d_out, int out_size) {
    const float* x    = (const float*)d_in[0];
    const float* Wq   = (const float*)d_in[1];
    const float* bq   = (const float*)d_in[2];
    const float* Wk   = (const float*)d_in[3];
    const float* bk   = (const float*)d_in[4];
    const float* Wv   = (const float*)d_in[5];
    const float* bv   = (const float*)d_in[6];
    const float* Wo   = (const float*)d_in[7];
    const float* bo   = (const float*)d_in[8];
    const float* proj = (const float*)d_in[9];
    float* out = (float*)d_out;

    cudaFuncSetAttribute(gemm_mma<1>, cudaFuncAttributeMaxDynamicSharedMemorySize, GSMEM);
    cudaFuncSetAttribute(gemm_mma<0>, cudaFuncAttributeMaxDynamicSharedMemorySize, GSMEM);
    cudaFuncSetAttribute(feat_mma<1>, cudaFuncAttributeMaxDynamicSharedMemorySize, FSMEM);
    cudaFuncSetAttribute(feat_mma<0>, cudaFuncAttributeMaxDynamicSharedMemorySize, FSMEM);

    init_kernel<<<6144, 256>>>(proj);
    split_x_kernel<<<(Bb*Nn*Dm)/256, 256>>>(x);
    split_w_kernel<<<(Dm*Dm)/256, 256>>>(Wq, 0);
    split_w_kernel<<<(Dm*Dm)/256, 256>>>(Wk, 1);
    split_w_kernel<<<(Dm*Dm)/256, 256>>>(Wv, 2);
    split_w_kernel<<<(Dm*Dm)/256, 256>>>(Wo, 3);

    gemm_mma<1><<<dim3(18, (Bb*Nn)/128), 256, GSMEM>>>(bq, bk, bv, nullptr);

    feat_mma<1><<<dim3(BH, Nn/64), 256, FSMEM>>>();   // qp (exp'd)
    feat_mma<0><<<dim3(BH, Nn/64), 256, FSMEM>>>();   // kp raw + kmax

    ctx_kernel<<<dim3(BH, 8), 256>>>();               // fused exp + ksum + ctx
    attn_out_kernel<<<dim3(BH, Nn/128), 256>>>();     // writes bf16 hi/lo direct

    gemm_mma<0><<<dim3(6, (Bb*Nn)/128), 256, GSMEM>>>(bo, bo, bo, out);
}